// round 2
// baseline (speedup 1.0000x reference)
#include <cuda_runtime.h>
#include <cuda_bf16.h>
#include <cstdint>

#define NUM_NODES 20000
#define SEQ_LEN 128
#define HIDDEN 32
#define N_TOTAL (NUM_NODES * SEQ_LEN)        // 2,560,000
#define N_EDGES 2000000

// Scratch: agg doubles as x_gcn (finalize is in-place). 327MB + 10MB.
__device__ float g_agg[(size_t)N_TOTAL * HIDDEN];
__device__ float g_deg[N_TOTAL];

// ---------------------------------------------------------------------------
// GCN kernels  (edge_index is int32: JAX x64-disabled downgrades int64->int32)
// ---------------------------------------------------------------------------

__global__ void deg_kernel(const int* __restrict__ ei, float* __restrict__ deg) {
    int e = blockIdx.x * blockDim.x + threadIdx.x;
    if (e < N_EDGES) {
        int dst = ei[N_EDGES + e];
        atomicAdd(deg + dst, 1.0f);
    }
}

// in-place: deg -> rsqrt(deg + 1)
__global__ void dinv_kernel(float* __restrict__ deg) {
    int i = blockIdx.x * blockDim.x + threadIdx.x;
    if (i < N_TOTAL) {
        deg[i] = rsqrtf(deg[i] + 1.0f);
    }
}

// warp per edge, lane = hidden channel. agg[dst*32+lane] += h[src][lane]*norm
__global__ void edge_scatter(const int* __restrict__ ei,
                             const float* __restrict__ x,
                             const float* __restrict__ dinv,
                             const float* __restrict__ gcnW,
                             float* __restrict__ agg) {
    int gtid = blockIdx.x * blockDim.x + threadIdx.x;
    int e = gtid >> 5;
    int lane = gtid & 31;
    if (e >= N_EDGES) return;
    int src = ei[e];
    int dst = ei[N_EDGES + e];
    float norm = dinv[src] * dinv[dst];
    float2 xv = *(const float2*)(x + 2 * (size_t)src);
    float h = xv.x * gcnW[lane] + xv.y * gcnW[32 + lane];
    atomicAdd(agg + (size_t)dst * 32 + lane, h * norm);
}

// warp per node: out = relu(agg + h*dinv^2 + b), in place in agg
__global__ void gcn_finalize(const float* __restrict__ x,
                             const float* __restrict__ dinv,
                             const float* __restrict__ gcnW,
                             const float* __restrict__ gcnb,
                             float* __restrict__ agg) {
    long long gtid = (long long)blockIdx.x * blockDim.x + threadIdx.x;
    int node = (int)(gtid >> 5);
    int lane = (int)(gtid & 31);
    if (node >= N_TOTAL) return;
    float2 xv = *(const float2*)(x + 2 * (size_t)node);
    float h = xv.x * gcnW[lane] + xv.y * gcnW[32 + lane];
    float di = dinv[node];
    size_t idx = (size_t)node * 32 + lane;
    float v = agg[idx] + h * di * di + gcnb[lane];
    agg[idx] = fmaxf(v, 0.0f);
}

// ---------------------------------------------------------------------------
// LSTM: thread per node, weights broadcast from SMEM, x/h in registers,
// h/c per-thread arrays in padded SMEM (dynamic index OK). FC fused at end.
// ---------------------------------------------------------------------------

__device__ __forceinline__ float fast_sigmoid(float v) {
    return __fdividef(1.0f, 1.0f + __expf(-v));
}
__device__ __forceinline__ float fast_tanh(float v) {
    v = fminf(15.0f, fmaxf(-15.0f, v));
    float e = __expf(2.0f * v);
    return __fdividef(e - 1.0f, e + 1.0f);
}

#define TPB_LSTM 64
#define H_PITCH 36   // float4-readable, conflict-free for vec loads
#define C_PITCH 33   // conflict-free for scalar access
// smem floats: wi 4096 | wh 4096 | bias 128 | fcw 32 | h TPB*36 | c TPB*33
#define SM_WI 0
#define SM_WH 4096
#define SM_BIAS 8192
#define SM_FCW 8320
#define SM_H 8352
#define SM_C (SM_H + TPB_LSTM * H_PITCH)
#define SM_FLOATS (SM_C + TPB_LSTM * C_PITCH)
#define SM_BYTES (SM_FLOATS * 4)

__global__ void __launch_bounds__(TPB_LSTM)
lstm_kernel(const float* __restrict__ xg,
            const float* __restrict__ w_ih, const float* __restrict__ w_hh,
            const float* __restrict__ b_ih, const float* __restrict__ b_hh,
            const float* __restrict__ fcW, const float* __restrict__ fcb,
            float* __restrict__ out) {
    extern __shared__ float sm[];
    float* s_wi = sm + SM_WI;
    float* s_wh = sm + SM_WH;
    float* s_bias = sm + SM_BIAS;
    float* s_fcw = sm + SM_FCW;
    int tid = threadIdx.x;

    for (int i = tid; i < 4096; i += TPB_LSTM) {
        s_wi[i] = w_ih[i];
        s_wh[i] = w_hh[i];
    }
    for (int i = tid; i < 128; i += TPB_LSTM) s_bias[i] = b_ih[i] + b_hh[i];
    if (tid < 32) s_fcw[tid] = fcW[tid];

    float* myh = sm + SM_H + tid * H_PITCH;
    float* myc = sm + SM_C + tid * C_PITCH;
#pragma unroll
    for (int u = 0; u < 32; u++) { myh[u] = 0.0f; myc[u] = 0.0f; }
    __syncthreads();

    int node0 = blockIdx.x * TPB_LSTM + tid;
    int node = node0 < NUM_NODES ? node0 : NUM_NODES - 1;
    const float4* xp = (const float4*)(xg + (size_t)node * SEQ_LEN * HIDDEN);

#pragma unroll 1
    for (int t = 0; t < SEQ_LEN; t++) {
        float4 xr[8], hr[8];
#pragma unroll
        for (int q = 0; q < 8; q++) xr[q] = xp[t * 8 + q];
#pragma unroll
        for (int q = 0; q < 8; q++) hr[q] = *(const float4*)(myh + 4 * q);

#pragma unroll 2
        for (int u = 0; u < 32; u++) {
            float ai = 0.f, af = 0.f, ag = 0.f, ao = 0.f;   // x parts
            float bi = 0.f, bf = 0.f, bg = 0.f, bo = 0.f;   // h parts
#pragma unroll
            for (int q = 0; q < 8; q++) {
                float4 x4 = xr[q];
                float4 h4 = hr[q];
                float4 w;
                // gate i : row u
                w = *(const float4*)(s_wi + (u) * 32 + 4 * q);
                ai = fmaf(x4.x, w.x, ai); ai = fmaf(x4.y, w.y, ai);
                ai = fmaf(x4.z, w.z, ai); ai = fmaf(x4.w, w.w, ai);
                w = *(const float4*)(s_wh + (u) * 32 + 4 * q);
                bi = fmaf(h4.x, w.x, bi); bi = fmaf(h4.y, w.y, bi);
                bi = fmaf(h4.z, w.z, bi); bi = fmaf(h4.w, w.w, bi);
                // gate f : row u+32
                w = *(const float4*)(s_wi + (u + 32) * 32 + 4 * q);
                af = fmaf(x4.x, w.x, af); af = fmaf(x4.y, w.y, af);
                af = fmaf(x4.z, w.z, af); af = fmaf(x4.w, w.w, af);
                w = *(const float4*)(s_wh + (u + 32) * 32 + 4 * q);
                bf = fmaf(h4.x, w.x, bf); bf = fmaf(h4.y, w.y, bf);
                bf = fmaf(h4.z, w.z, bf); bf = fmaf(h4.w, w.w, bf);
                // gate g : row u+64
                w = *(const float4*)(s_wi + (u + 64) * 32 + 4 * q);
                ag = fmaf(x4.x, w.x, ag); ag = fmaf(x4.y, w.y, ag);
                ag = fmaf(x4.z, w.z, ag); ag = fmaf(x4.w, w.w, ag);
                w = *(const float4*)(s_wh + (u + 64) * 32 + 4 * q);
                bg = fmaf(h4.x, w.x, bg); bg = fmaf(h4.y, w.y, bg);
                bg = fmaf(h4.z, w.z, bg); bg = fmaf(h4.w, w.w, bg);
                // gate o : row u+96
                w = *(const float4*)(s_wi + (u + 96) * 32 + 4 * q);
                ao = fmaf(x4.x, w.x, ao); ao = fmaf(x4.y, w.y, ao);
                ao = fmaf(x4.z, w.z, ao); ao = fmaf(x4.w, w.w, ao);
                w = *(const float4*)(s_wh + (u + 96) * 32 + 4 * q);
                bo = fmaf(h4.x, w.x, bo); bo = fmaf(h4.y, w.y, bo);
                bo = fmaf(h4.z, w.z, bo); bo = fmaf(h4.w, w.w, bo);
            }
            float gi = fast_sigmoid(ai + bi + s_bias[u]);
            float gf = fast_sigmoid(af + bf + s_bias[32 + u]);
            float gg = fast_tanh(ag + bg + s_bias[64 + u]);
            float go = fast_sigmoid(ao + bo + s_bias[96 + u]);
            float c = gf * myc[u] + gi * gg;
            myc[u] = c;
            myh[u] = go * fast_tanh(c);
        }
    }

    if (node0 < NUM_NODES) {
        float acc = fcb[0];
#pragma unroll
        for (int u = 0; u < 32; u++) acc = fmaf(myh[u], s_fcw[u], acc);
        out[node0] = acc;
    }
}

// ---------------------------------------------------------------------------

extern "C" void kernel_launch(void* const* d_in, const int* in_sizes, int n_in,
                              void* d_out, int out_size) {
    const float* x = (const float*)d_in[0];
    const int* ei = (const int*)d_in[1];
    const float* gcnW = (const float*)d_in[2];
    const float* gcnb = (const float*)d_in[3];
    const float* w_ih = (const float*)d_in[4];
    const float* w_hh = (const float*)d_in[5];
    const float* b_ih = (const float*)d_in[6];
    const float* b_hh = (const float*)d_in[7];
    const float* fcW = (const float*)d_in[8];
    const float* fcb = (const float*)d_in[9];
    float* out = (float*)d_out;

    void* aggp = nullptr;
    void* degp = nullptr;
    cudaGetSymbolAddress(&aggp, g_agg);
    cudaGetSymbolAddress(&degp, g_deg);

    cudaMemsetAsync(aggp, 0, sizeof(float) * (size_t)N_TOTAL * HIDDEN);
    cudaMemsetAsync(degp, 0, sizeof(float) * (size_t)N_TOTAL);

    deg_kernel<<<(N_EDGES + 255) / 256, 256>>>(ei, (float*)degp);
    dinv_kernel<<<(N_TOTAL + 255) / 256, 256>>>((float*)degp);

    {
        long long threads = (long long)N_EDGES * 32;
        int blocks = (int)((threads + 255) / 256);
        edge_scatter<<<blocks, 256>>>(ei, x, (const float*)degp, gcnW, (float*)aggp);
    }
    {
        long long threads = (long long)N_TOTAL * 32;
        int blocks = (int)((threads + 255) / 256);
        gcn_finalize<<<blocks, 256>>>(x, (const float*)degp, gcnW, gcnb, (float*)aggp);
    }

    cudaFuncSetAttribute(lstm_kernel, cudaFuncAttributeMaxDynamicSharedMemorySize, SM_BYTES);
    int lstm_blocks = (NUM_NODES + TPB_LSTM - 1) / TPB_LSTM;
    lstm_blocks = lstm_blocks;
    lstm_kernel<<<lstm_blocks, TPB_LSTM, SM_BYTES>>>(
        (const float*)aggp, w_ih, w_hh, b_ih, b_hh, fcW, fcb, out);
}

// round 3
// speedup vs baseline: 1.3081x; 1.3081x over previous
#include <cuda_runtime.h>
#include <cuda_bf16.h>
#include <cstdint>

#define NUM_NODES 20000
#define SEQ_LEN 128
#define HIDDEN 32
#define N_TOTAL (NUM_NODES * SEQ_LEN)        // 2,560,000
#define N_EDGES 2000000

// Scratch: pre-transform aggregate (2 floats per position) + degree. 20MB + 10MB.
__device__ float g_agg2[(size_t)N_TOTAL * 2];
__device__ float g_deg[N_TOTAL];

// ---------------------------------------------------------------------------
// GCN kernels (edge_index arrives as int32)
// ---------------------------------------------------------------------------

__global__ void deg_kernel(const int* __restrict__ ei, float* __restrict__ deg) {
    int e = blockIdx.x * blockDim.x + threadIdx.x;
    if (e < N_EDGES) {
        int dst = ei[N_EDGES + e];
        atomicAdd(deg + dst, 1.0f);
    }
}

// in-place: deg -> rsqrt(deg + 1)
__global__ void dinv_kernel(float* __restrict__ deg) {
    int i = blockIdx.x * blockDim.x + threadIdx.x;
    if (i < N_TOTAL) {
        deg[i] = rsqrtf(deg[i] + 1.0f);
    }
}

// thread per edge: agg2[dst] += x[src] * norm   (GCN linearity: W applied later)
__global__ void edge_scatter2(const int* __restrict__ ei,
                              const float* __restrict__ x,
                              const float* __restrict__ dinv,
                              float* __restrict__ agg2) {
    int e = blockIdx.x * blockDim.x + threadIdx.x;
    if (e >= N_EDGES) return;
    int src = ei[e];
    int dst = ei[N_EDGES + e];
    float norm = dinv[src] * dinv[dst];
    float2 xv = *(const float2*)(x + 2 * (size_t)src);
    float* p = agg2 + 2 * (size_t)dst;
    atomicAdd(p, xv.x * norm);
    atomicAdd(p + 1, xv.y * norm);
}

// ---------------------------------------------------------------------------
// LSTM: thread per node, TPB=128 (covers all 4 SMSPs). Weights broadcast from
// SMEM; x_gcn computed inline from agg2/x/dinv (GCN finalize fused); h/c in
// padded SMEM per thread; FC fused at the end.
// ---------------------------------------------------------------------------

__device__ __forceinline__ float fast_sigmoid(float v) {
    return __fdividef(1.0f, 1.0f + __expf(-v));
}
__device__ __forceinline__ float fast_tanh(float v) {
    v = fminf(15.0f, fmaxf(-15.0f, v));
    float e = __expf(2.0f * v);
    return __fdividef(e - 1.0f, e + 1.0f);
}

#define TPB_LSTM 128
#define H_PITCH 36   // float4-readable, conflict-free
#define C_PITCH 33
// smem floats: wi 4096 | wh 4096 | bias 128 | fcw 32 | gw0 32 | gw1 32 | gb 32
//            | h TPB*36 | c TPB*33
#define SM_WI 0
#define SM_WH 4096
#define SM_BIAS 8192
#define SM_FCW 8320
#define SM_GW0 8352
#define SM_GW1 8384
#define SM_GB 8416
#define SM_H 8448
#define SM_C (SM_H + TPB_LSTM * H_PITCH)
#define SM_FLOATS (SM_C + TPB_LSTM * C_PITCH)
#define SM_BYTES (SM_FLOATS * 4)

__global__ void __launch_bounds__(TPB_LSTM)
lstm_kernel(const float* __restrict__ xg2,     // raw input x [N_TOTAL,2]
            const float* __restrict__ agg2,    // scattered aggregate [N_TOTAL,2]
            const float* __restrict__ dinv,    // [N_TOTAL]
            const float* __restrict__ gcnW, const float* __restrict__ gcnb,
            const float* __restrict__ w_ih, const float* __restrict__ w_hh,
            const float* __restrict__ b_ih, const float* __restrict__ b_hh,
            const float* __restrict__ fcW, const float* __restrict__ fcb,
            float* __restrict__ out) {
    extern __shared__ float sm[];
    float* s_wi = sm + SM_WI;
    float* s_wh = sm + SM_WH;
    float* s_bias = sm + SM_BIAS;
    float* s_fcw = sm + SM_FCW;
    float* s_gw0 = sm + SM_GW0;
    float* s_gw1 = sm + SM_GW1;
    float* s_gb = sm + SM_GB;
    int tid = threadIdx.x;

    for (int i = tid; i < 4096; i += TPB_LSTM) {
        s_wi[i] = w_ih[i];
        s_wh[i] = w_hh[i];
    }
    if (tid < 128) s_bias[tid] = b_ih[tid] + b_hh[tid];
    if (tid < 32) {
        s_fcw[tid] = fcW[tid];
        s_gw0[tid] = gcnW[tid];        // gcn_W[0, u]
        s_gw1[tid] = gcnW[32 + tid];   // gcn_W[1, u]
        s_gb[tid] = gcnb[tid];
    }

    float* myh = sm + SM_H + tid * H_PITCH;
    float* myc = sm + SM_C + tid * C_PITCH;
#pragma unroll
    for (int u = 0; u < 32; u++) { myh[u] = 0.0f; myc[u] = 0.0f; }
    __syncthreads();

    int node0 = blockIdx.x * TPB_LSTM + tid;
    int node = node0 < NUM_NODES ? node0 : NUM_NODES - 1;
    const float2* xp = (const float2*)(xg2 + (size_t)node * SEQ_LEN * 2);
    const float2* ap = (const float2*)(agg2 + (size_t)node * SEQ_LEN * 2);
    const float* dp = dinv + (size_t)node * SEQ_LEN;

#pragma unroll 1
    for (int t = 0; t < SEQ_LEN; t++) {
        // ---- fused GCN finalize: x_gcn[u] = relu(v0*W0u + v1*W1u + gb[u])
        float2 xv = xp[t];
        float2 av = ap[t];
        float di = dp[t];
        float d2 = di * di;
        float v0 = fmaf(xv.x, d2, av.x);
        float v1 = fmaf(xv.y, d2, av.y);

        float4 xr[8], hr[8];
#pragma unroll
        for (int q = 0; q < 8; q++) {
            float4 g;
            g.x = fmaxf(fmaf(v0, s_gw0[4 * q + 0], fmaf(v1, s_gw1[4 * q + 0], s_gb[4 * q + 0])), 0.0f);
            g.y = fmaxf(fmaf(v0, s_gw0[4 * q + 1], fmaf(v1, s_gw1[4 * q + 1], s_gb[4 * q + 1])), 0.0f);
            g.z = fmaxf(fmaf(v0, s_gw0[4 * q + 2], fmaf(v1, s_gw1[4 * q + 2], s_gb[4 * q + 2])), 0.0f);
            g.w = fmaxf(fmaf(v0, s_gw0[4 * q + 3], fmaf(v1, s_gw1[4 * q + 3], s_gb[4 * q + 3])), 0.0f);
            xr[q] = g;
        }
#pragma unroll
        for (int q = 0; q < 8; q++) hr[q] = *(const float4*)(myh + 4 * q);

#pragma unroll 2
        for (int u = 0; u < 32; u++) {
            float ai = 0.f, af = 0.f, ag = 0.f, ao = 0.f;   // x parts
            float bi = 0.f, bf = 0.f, bg = 0.f, bo = 0.f;   // h parts
#pragma unroll
            for (int q = 0; q < 8; q++) {
                float4 x4 = xr[q];
                float4 h4 = hr[q];
                float4 w;
                // gate i : row u
                w = *(const float4*)(s_wi + (u) * 32 + 4 * q);
                ai = fmaf(x4.x, w.x, ai); ai = fmaf(x4.y, w.y, ai);
                ai = fmaf(x4.z, w.z, ai); ai = fmaf(x4.w, w.w, ai);
                w = *(const float4*)(s_wh + (u) * 32 + 4 * q);
                bi = fmaf(h4.x, w.x, bi); bi = fmaf(h4.y, w.y, bi);
                bi = fmaf(h4.z, w.z, bi); bi = fmaf(h4.w, w.w, bi);
                // gate f : row u+32
                w = *(const float4*)(s_wi + (u + 32) * 32 + 4 * q);
                af = fmaf(x4.x, w.x, af); af = fmaf(x4.y, w.y, af);
                af = fmaf(x4.z, w.z, af); af = fmaf(x4.w, w.w, af);
                w = *(const float4*)(s_wh + (u + 32) * 32 + 4 * q);
                bf = fmaf(h4.x, w.x, bf); bf = fmaf(h4.y, w.y, bf);
                bf = fmaf(h4.z, w.z, bf); bf = fmaf(h4.w, w.w, bf);
                // gate g : row u+64
                w = *(const float4*)(s_wi + (u + 64) * 32 + 4 * q);
                ag = fmaf(x4.x, w.x, ag); ag = fmaf(x4.y, w.y, ag);
                ag = fmaf(x4.z, w.z, ag); ag = fmaf(x4.w, w.w, ag);
                w = *(const float4*)(s_wh + (u + 64) * 32 + 4 * q);
                bg = fmaf(h4.x, w.x, bg); bg = fmaf(h4.y, w.y, bg);
                bg = fmaf(h4.z, w.z, bg); bg = fmaf(h4.w, w.w, bg);
                // gate o : row u+96
                w = *(const float4*)(s_wi + (u + 96) * 32 + 4 * q);
                ao = fmaf(x4.x, w.x, ao); ao = fmaf(x4.y, w.y, ao);
                ao = fmaf(x4.z, w.z, ao); ao = fmaf(x4.w, w.w, ao);
                w = *(const float4*)(s_wh + (u + 96) * 32 + 4 * q);
                bo = fmaf(h4.x, w.x, bo); bo = fmaf(h4.y, w.y, bo);
                bo = fmaf(h4.z, w.z, bo); bo = fmaf(h4.w, w.w, bo);
            }
            float gi = fast_sigmoid(ai + bi + s_bias[u]);
            float gf = fast_sigmoid(af + bf + s_bias[32 + u]);
            float gg = fast_tanh(ag + bg + s_bias[64 + u]);
            float go = fast_sigmoid(ao + bo + s_bias[96 + u]);
            float c = gf * myc[u] + gi * gg;
            myc[u] = c;
            myh[u] = go * fast_tanh(c);
        }
    }

    if (node0 < NUM_NODES) {
        float acc = fcb[0];
#pragma unroll
        for (int u = 0; u < 32; u++) acc = fmaf(myh[u], s_fcw[u], acc);
        out[node0] = acc;
    }
}

// ---------------------------------------------------------------------------

extern "C" void kernel_launch(void* const* d_in, const int* in_sizes, int n_in,
                              void* d_out, int out_size) {
    const float* x = (const float*)d_in[0];
    const int* ei = (const int*)d_in[1];
    const float* gcnW = (const float*)d_in[2];
    const float* gcnb = (const float*)d_in[3];
    const float* w_ih = (const float*)d_in[4];
    const float* w_hh = (const float*)d_in[5];
    const float* b_ih = (const float*)d_in[6];
    const float* b_hh = (const float*)d_in[7];
    const float* fcW = (const float*)d_in[8];
    const float* fcb = (const float*)d_in[9];
    float* out = (float*)d_out;

    void* aggp = nullptr;
    void* degp = nullptr;
    cudaGetSymbolAddress(&aggp, g_agg2);
    cudaGetSymbolAddress(&degp, g_deg);

    cudaMemsetAsync(aggp, 0, sizeof(float) * (size_t)N_TOTAL * 2);
    cudaMemsetAsync(degp, 0, sizeof(float) * (size_t)N_TOTAL);

    deg_kernel<<<(N_EDGES + 255) / 256, 256>>>(ei, (float*)degp);
    dinv_kernel<<<(N_TOTAL + 255) / 256, 256>>>((float*)degp);
    edge_scatter2<<<(N_EDGES + 255) / 256, 256>>>(ei, x, (const float*)degp, (float*)aggp);

    cudaFuncSetAttribute(lstm_kernel, cudaFuncAttributeMaxDynamicSharedMemorySize, SM_BYTES);
    int lstm_blocks = (NUM_NODES + TPB_LSTM - 1) / TPB_LSTM;
    lstm_kernel<<<lstm_blocks, TPB_LSTM, SM_BYTES>>>(
        x, (const float*)aggp, (const float*)degp, gcnW, gcnb,
        w_ih, w_hh, b_ih, b_hh, fcW, fcb, out);
}